// round 1
// baseline (speedup 1.0000x reference)
#include <cuda_runtime.h>
#include <cuda_bf16.h>
#include <cstdint>

// Problem constants (fixed by the dataset)
#define TQ    16384          // tokens = B*S
#define HD    1024           // hidden
#define ID    3584           // intermediate
#define NE    8              // experts
#define NSLOT (TQ * 2)       // top-k = 2
#define MAXTILES 320         // >= sum ceil(cnt_e/128) worst case (264)

// ---------------- device scratch (static; no allocations allowed) ----------
__device__ float    g_hid[(size_t)NSLOT * ID];     // SwiGLU intermediate, ~470MB
__device__ int      g_tok[NE * TQ];                // token index per (expert, row)
__device__ float    g_wt [NE * TQ];                // combine weight per (expert, row)
__device__ int      g_cnt[NE];
__device__ int      g_offs[NE + 1];
__device__ int      g_tile_e[MAXTILES];
__device__ int      g_tile_r[MAXTILES];
__device__ int      g_ntiles;

// ---------------- helpers --------------------------------------------------
__device__ __forceinline__ unsigned f2tf(float f) {
    unsigned u;
    asm("cvt.rna.tf32.f32 %0, %1;" : "=r"(u) : "f"(f));
    return u;
}

__device__ __forceinline__ void mma_tf32(float c[4], const unsigned a[4],
                                         unsigned b0, unsigned b1) {
    asm volatile(
        "mma.sync.aligned.m16n8k8.row.col.f32.tf32.tf32.f32 "
        "{%0,%1,%2,%3}, {%4,%5,%6,%7}, {%8,%9}, {%0,%1,%2,%3};"
        : "+f"(c[0]), "+f"(c[1]), "+f"(c[2]), "+f"(c[3])
        : "r"(a[0]), "r"(a[1]), "r"(a[2]), "r"(a[3]), "r"(b0), "r"(b1));
}

__device__ __forceinline__ float silu(float x) {
    return x / (1.0f + __expf(-x));
}

// ---------------- kernel: zero counters ------------------------------------
__global__ void k_zero() {
    if (threadIdx.x < NE) g_cnt[threadIdx.x] = 0;
}

// ---------------- kernel: router (one warp per token) -----------------------
__global__ void k_router(const float* __restrict__ x, const float* __restrict__ gw) {
    int gwarp = (blockIdx.x * blockDim.x + threadIdx.x) >> 5;
    int lane  = threadIdx.x & 31;
    if (gwarp >= TQ) return;
    const float* xr = x + (size_t)gwarp * HD;

    float acc[NE];
#pragma unroll
    for (int e = 0; e < NE; e++) acc[e] = 0.0f;

#pragma unroll 4
    for (int j = 0; j < HD / 32; j++) {
        int h = lane + j * 32;
        float xv = xr[h];
#pragma unroll
        for (int e = 0; e < NE; e++) acc[e] += xv * gw[e * HD + h];
    }
#pragma unroll
    for (int e = 0; e < NE; e++) {
#pragma unroll
        for (int o = 16; o > 0; o >>= 1)
            acc[e] += __shfl_xor_sync(0xFFFFFFFFu, acc[e], o);
    }
    if (lane == 0) {
        // top-2 on logits (same order as softmax probs); ties -> lower index
        int i0 = 0;
#pragma unroll
        for (int e = 1; e < NE; e++) if (acc[e] > acc[i0]) i0 = e;
        int i1 = (i0 == 0) ? 1 : 0;
#pragma unroll
        for (int e = 0; e < NE; e++) if (e != i0 && acc[e] > acc[i1]) i1 = e;
        // renormalized top-2 softmax weights: p0/(p0+p1) = 1/(1+exp(l1-l0))
        float w0 = 1.0f / (1.0f + expf(acc[i1] - acc[i0]));
        float w1 = 1.0f - w0;
        int p0 = atomicAdd(&g_cnt[i0], 1);
        g_tok[i0 * TQ + p0] = gwarp;  g_wt[i0 * TQ + p0] = w0;
        int p1 = atomicAdd(&g_cnt[i1], 1);
        g_tok[i1 * TQ + p1] = gwarp;  g_wt[i1 * TQ + p1] = w1;
    }
}

// ---------------- kernel: finalize offsets + tile table ----------------------
__global__ void k_finalize() {
    if (threadIdx.x != 0 || blockIdx.x != 0) return;
    int o = 0;
    g_offs[0] = 0;
    for (int e = 0; e < NE; e++) { o += g_cnt[e]; g_offs[e + 1] = o; }
    int nt = 0;
    for (int e = 0; e < NE; e++) {
        for (int r = 0; r < g_cnt[e] && nt < MAXTILES; r += 128) {
            g_tile_e[nt] = e; g_tile_r[nt] = r; nt++;
        }
    }
    g_ntiles = nt;
}

// ---------------- pass1: hid = silu(Xg @ W1) * (Xg @ W3) ---------------------
// block tile: M=128, N=64 (per matrix, shared A), K-chunk 32; 256 thr = 8 warps (4x2)
__global__ void __launch_bounds__(256) k_pass1(const float* __restrict__ x,
                                               const float* __restrict__ w1,
                                               const float* __restrict__ w3) {
    int mt = blockIdx.y;
    if (mt >= g_ntiles) return;
    const int e   = g_tile_e[mt];
    const int r0  = g_tile_r[mt];
    const int cnt = g_cnt[e];
    const int n0  = blockIdx.x * 64;

    __shared__ unsigned As[128][36];
    __shared__ unsigned B1s[32][68];
    __shared__ unsigned B3s[32][68];

    const int tid  = threadIdx.x;
    const int lane = tid & 31, warp = tid >> 5;
    const int wm = warp >> 1, wn = warp & 1;
    const int gid = lane >> 2, tig = lane & 3;

    // A-load mapping: 2 threads per row, 16 floats each
    const int arow  = tid >> 1;
    const int ahalf = tid & 1;
    int tokr = -1;
    if (r0 + arow < cnt) tokr = g_tok[e * TQ + r0 + arow];
    const float* xp = (tokr >= 0) ? (x + (size_t)tokr * HD) : x;

    const float* w1p = w1 + (size_t)e * HD * ID;
    const float* w3p = w3 + (size_t)e * HD * ID;

    float acc1[2][4][4], acc3[2][4][4];
#pragma unroll
    for (int mi = 0; mi < 2; mi++)
#pragma unroll
        for (int ni = 0; ni < 4; ni++)
#pragma unroll
            for (int q = 0; q < 4; q++) { acc1[mi][ni][q] = 0.f; acc3[mi][ni][q] = 0.f; }

    for (int kc = 0; kc < HD / 32; kc++) {
        const int k0 = kc * 32;
        // ---- load A tile (gathered, tf32-converted) ----
        if (tokr >= 0) {
#pragma unroll
            for (int q = 0; q < 4; q++) {
                float4 v = *(const float4*)(xp + k0 + ahalf * 16 + q * 4);
                As[arow][ahalf * 16 + q * 4 + 0] = f2tf(v.x);
                As[arow][ahalf * 16 + q * 4 + 1] = f2tf(v.y);
                As[arow][ahalf * 16 + q * 4 + 2] = f2tf(v.z);
                As[arow][ahalf * 16 + q * 4 + 3] = f2tf(v.w);
            }
        } else {
#pragma unroll
            for (int q = 0; q < 16; q++) As[arow][ahalf * 16 + q] = 0u;
        }
        // ---- load B tiles ----
#pragma unroll
        for (int it = 0; it < 2; it++) {
            int idx = tid + it * 256;
            int kr = idx >> 4, c4 = idx & 15;
            const float4 v1 = *(const float4*)(w1p + (size_t)(k0 + kr) * ID + n0 + c4 * 4);
            const float4 v3 = *(const float4*)(w3p + (size_t)(k0 + kr) * ID + n0 + c4 * 4);
            B1s[kr][c4 * 4 + 0] = f2tf(v1.x); B1s[kr][c4 * 4 + 1] = f2tf(v1.y);
            B1s[kr][c4 * 4 + 2] = f2tf(v1.z); B1s[kr][c4 * 4 + 3] = f2tf(v1.w);
            B3s[kr][c4 * 4 + 0] = f2tf(v3.x); B3s[kr][c4 * 4 + 1] = f2tf(v3.y);
            B3s[kr][c4 * 4 + 2] = f2tf(v3.z); B3s[kr][c4 * 4 + 3] = f2tf(v3.w);
        }
        __syncthreads();
        // ---- compute ----
#pragma unroll
        for (int ks = 0; ks < 4; ks++) {
            const int kk = ks * 8;
            unsigned a[2][4];
#pragma unroll
            for (int mi = 0; mi < 2; mi++) {
                int r = wm * 32 + mi * 16;
                a[mi][0] = As[r + gid][kk + tig];
                a[mi][1] = As[r + gid + 8][kk + tig];
                a[mi][2] = As[r + gid][kk + tig + 4];
                a[mi][3] = As[r + gid + 8][kk + tig + 4];
            }
#pragma unroll
            for (int ni = 0; ni < 4; ni++) {
                int cc = wn * 32 + ni * 8 + gid;
                unsigned b10 = B1s[kk + tig][cc], b11 = B1s[kk + tig + 4][cc];
                unsigned b30 = B3s[kk + tig][cc], b31 = B3s[kk + tig + 4][cc];
#pragma unroll
                for (int mi = 0; mi < 2; mi++) {
                    mma_tf32(acc1[mi][ni], a[mi], b10, b11);
                    mma_tf32(acc3[mi][ni], a[mi], b30, b31);
                }
            }
        }
        __syncthreads();
    }

    // ---- epilogue: SwiGLU -> g_hid ----
    const int gofs = g_offs[e];
#pragma unroll
    for (int mi = 0; mi < 2; mi++) {
#pragma unroll
        for (int ni = 0; ni < 4; ni++) {
            int col = n0 + wn * 32 + ni * 8 + tig * 2;
            int rl0 = r0 + wm * 32 + mi * 16 + gid;
            if (rl0 < cnt) {
                float2 h;
                h.x = silu(acc1[mi][ni][0]) * acc3[mi][ni][0];
                h.y = silu(acc1[mi][ni][1]) * acc3[mi][ni][1];
                *(float2*)&g_hid[(size_t)(gofs + rl0) * ID + col] = h;
            }
            int rl1 = rl0 + 8;
            if (rl1 < cnt) {
                float2 h;
                h.x = silu(acc1[mi][ni][2]) * acc3[mi][ni][2];
                h.y = silu(acc1[mi][ni][3]) * acc3[mi][ni][3];
                *(float2*)&g_hid[(size_t)(gofs + rl1) * ID + col] = h;
            }
        }
    }
}

// ---------------- pass2: out[token] += wt * (hid @ W2) -----------------------
// block tile: M=128, N=128, K-chunk 32; 8 warps (4x2), warp tile 32x64
__global__ void __launch_bounds__(256) k_pass2(const float* __restrict__ w2,
                                               float* __restrict__ out) {
    int mt = blockIdx.y;
    if (mt >= g_ntiles) return;
    const int e   = g_tile_e[mt];
    const int r0  = g_tile_r[mt];
    const int cnt = g_cnt[e];
    const int n0  = blockIdx.x * 128;
    const int gofs = g_offs[e];

    __shared__ unsigned As[128][36];
    __shared__ unsigned Bs[32][132];

    const int tid  = threadIdx.x;
    const int lane = tid & 31, warp = tid >> 5;
    const int wm = warp >> 1, wn = warp & 1;
    const int gid = lane >> 2, tig = lane & 3;

    const int arow  = tid >> 1;
    const int ahalf = tid & 1;
    const bool avalid = (r0 + arow < cnt);
    const float* ap = g_hid + (size_t)(gofs + r0 + arow) * ID;

    const float* w2p = w2 + (size_t)e * ID * HD;

    float acc[2][8][4];
#pragma unroll
    for (int mi = 0; mi < 2; mi++)
#pragma unroll
        for (int ni = 0; ni < 8; ni++)
#pragma unroll
            for (int q = 0; q < 4; q++) acc[mi][ni][q] = 0.f;

    for (int kc = 0; kc < ID / 32; kc++) {
        const int k0 = kc * 32;
        if (avalid) {
#pragma unroll
            for (int q = 0; q < 4; q++) {
                float4 v = *(const float4*)(ap + k0 + ahalf * 16 + q * 4);
                As[arow][ahalf * 16 + q * 4 + 0] = f2tf(v.x);
                As[arow][ahalf * 16 + q * 4 + 1] = f2tf(v.y);
                As[arow][ahalf * 16 + q * 4 + 2] = f2tf(v.z);
                As[arow][ahalf * 16 + q * 4 + 3] = f2tf(v.w);
            }
        } else {
#pragma unroll
            for (int q = 0; q < 16; q++) As[arow][ahalf * 16 + q] = 0u;
        }
#pragma unroll
        for (int it = 0; it < 4; it++) {
            int idx = tid + it * 256;
            int kr = idx >> 5, c4 = idx & 31;
            const float4 v = *(const float4*)(w2p + (size_t)(k0 + kr) * HD + n0 + c4 * 4);
            Bs[kr][c4 * 4 + 0] = f2tf(v.x); Bs[kr][c4 * 4 + 1] = f2tf(v.y);
            Bs[kr][c4 * 4 + 2] = f2tf(v.z); Bs[kr][c4 * 4 + 3] = f2tf(v.w);
        }
        __syncthreads();
#pragma unroll
        for (int ks = 0; ks < 4; ks++) {
            const int kk = ks * 8;
            unsigned a[2][4];
#pragma unroll
            for (int mi = 0; mi < 2; mi++) {
                int r = wm * 32 + mi * 16;
                a[mi][0] = As[r + gid][kk + tig];
                a[mi][1] = As[r + gid + 8][kk + tig];
                a[mi][2] = As[r + gid][kk + tig + 4];
                a[mi][3] = As[r + gid + 8][kk + tig + 4];
            }
#pragma unroll
            for (int ni = 0; ni < 8; ni++) {
                int cc = wn * 64 + ni * 8 + gid;
                unsigned b0 = Bs[kk + tig][cc], b1 = Bs[kk + tig + 4][cc];
#pragma unroll
                for (int mi = 0; mi < 2; mi++) mma_tf32(acc[mi][ni], a[mi], b0, b1);
            }
        }
        __syncthreads();
    }

    // ---- epilogue: weighted scatter-add (exactly 2 commutative adds/token) ----
#pragma unroll
    for (int mi = 0; mi < 2; mi++) {
#pragma unroll
        for (int half = 0; half < 2; half++) {
            int rl = r0 + wm * 32 + mi * 16 + gid + half * 8;
            if (rl >= cnt) continue;
            int   tok = g_tok[e * TQ + rl];
            float wgt = g_wt[e * TQ + rl];
            float* op = out + (size_t)tok * HD;
#pragma unroll
            for (int ni = 0; ni < 8; ni++) {
                int col = n0 + wn * 64 + ni * 8 + tig * 2;
                atomicAdd(op + col,     acc[mi][ni][half * 2 + 0] * wgt);
                atomicAdd(op + col + 1, acc[mi][ni][half * 2 + 1] * wgt);
            }
        }
    }
}

// ---------------- launch ----------------------------------------------------
extern "C" void kernel_launch(void* const* d_in, const int* in_sizes, int n_in,
                              void* d_out, int out_size) {
    const float* x  = (const float*)d_in[0];
    const float* gw = (const float*)d_in[1];
    const float* w1 = (const float*)d_in[2];
    const float* w3 = (const float*)d_in[3];
    const float* w2 = (const float*)d_in[4];
    float* out = (float*)d_out;

    cudaMemsetAsync(out, 0, (size_t)out_size * sizeof(float));
    k_zero<<<1, 32>>>();
    k_router<<<TQ / 8, 256>>>(x, gw);
    k_finalize<<<1, 1>>>();
    // grid.x = n-tiles (fast) so a wave = few m-tiles x all n-tiles -> L2 reuse
    k_pass1<<<dim3(ID / 64, MAXTILES), 256>>>(x, w1, w3);
    k_pass2<<<dim3(HD / 128, MAXTILES), 256>>>(w2, out);
}

// round 5
// speedup vs baseline: 1.1115x; 1.1115x over previous
#include <cuda_runtime.h>
#include <cstdint>

// Problem constants
#define TQ    16384
#define HD    1024
#define ID    3584
#define NE    8
#define MAXTILES 320
#define KC    32
#define NK1   (HD/KC)            // 32
#define NK2   (ID/KC)            // 112

// pass1 tile: M=128, N=64 per matrix (w1+w3), 8 warps (4 wm x 2 wn), warp 32x32
// pass2 tile: M=128, N=128, 8 warps (4 wm x 2 wn), warp 32x64

// smem stage layouts (bytes)
#define P1_A_OFF   0
#define P1_AROWB   144                        // 32 floats + 4 pad words
#define P1_B1_OFF  (128*144)                  // 18432
#define P1_BROWB   288                        // 64 floats + 8 pad words (stride 72 w)
#define P1_B3_OFF  (P1_B1_OFF + 32*288)       // 27648
#define P1_STAGE   (P1_B3_OFF + 32*288)       // 36864
#define P1_SMEM    (2*P1_STAGE)               // 73728

#define P2_A_OFF   0
#define P2_B_OFF   (128*144)                  // 18432
#define P2_BROWB   544                        // 128 floats + 8 pad words (stride 136 w)
#define P2_STAGE   (P2_B_OFF + 32*544)        // 35840
#define P2_SMEM    (2*P2_STAGE)               // 71680

// ---------------- device scratch ----------------
__device__ float g_hid [(size_t)TQ * 2 * ID];   // SwiGLU intermediate
__device__ float g_part[(size_t)TQ * 2 * HD];   // weighted per-slot outputs
__device__ int   g_tok[NE * TQ];
__device__ float g_wt [NE * TQ];
__device__ int   g_se [TQ * 2];                 // token -> expert (2 slots)
__device__ int   g_sp [TQ * 2];                 // token -> row within expert
__device__ int   g_cnt[NE];
__device__ int   g_offs[NE + 1];
__device__ int   g_tile_e[MAXTILES];
__device__ int   g_tile_r[MAXTILES];
__device__ int   g_ntiles;

// ---------------- helpers ----------------
__device__ __forceinline__ uint32_t smem_u32(const void* p) {
    uint32_t a;
    asm("{ .reg .u64 t; cvta.to.shared.u64 t, %1; cvt.u32.u64 %0, t; }" : "=r"(a) : "l"(p));
    return a;
}
__device__ __forceinline__ unsigned f2tf(float f) {
    unsigned u; asm("cvt.rna.tf32.f32 %0, %1;" : "=r"(u) : "f"(f)); return u;
}
__device__ __forceinline__ unsigned u2tf(unsigned raw) {   // raw fp32 bits -> tf32
    unsigned u; asm("cvt.rna.tf32.f32 %0, %1;" : "=r"(u) : "f"(__uint_as_float(raw))); return u;
}
__device__ __forceinline__ float silu(float x) { return x / (1.0f + __expf(-x)); }

__device__ __forceinline__ void mma_tf32(float c[4], const unsigned a[4],
                                         unsigned b0, unsigned b1) {
    asm volatile(
        "mma.sync.aligned.m16n8k8.row.col.f32.tf32.tf32.f32 "
        "{%0,%1,%2,%3}, {%4,%5,%6,%7}, {%8,%9}, {%0,%1,%2,%3};"
        : "+f"(c[0]), "+f"(c[1]), "+f"(c[2]), "+f"(c[3])
        : "r"(a[0]), "r"(a[1]), "r"(a[2]), "r"(a[3]), "r"(b0), "r"(b1));
}

#define LDSM4(r0, r1, r2, r3, addr)                                              \
    asm volatile("ldmatrix.sync.aligned.m8n8.x4.shared.b16 {%0,%1,%2,%3}, [%4];" \
        : "=r"(r0), "=r"(r1), "=r"(r2), "=r"(r3) : "r"(addr))

#define CP_ASYNC16(dst, src) \
    asm volatile("cp.async.cg.shared.global [%0], [%1], 16;" :: "r"(dst), "l"(src))
#define CP_COMMIT()  asm volatile("cp.async.commit_group;" ::: "memory")
#define CP_WAIT(n)   asm volatile("cp.async.wait_group %0;" :: "n"(n) : "memory")

// ---------------- small kernels ----------------
__global__ void k_zero() { if (threadIdx.x < NE) g_cnt[threadIdx.x] = 0; }

__global__ void k_router(const float* __restrict__ x, const float* __restrict__ gw) {
    int gwarp = (blockIdx.x * blockDim.x + threadIdx.x) >> 5;
    int lane  = threadIdx.x & 31;
    if (gwarp >= TQ) return;
    const float* xr = x + (size_t)gwarp * HD;
    float acc[NE];
#pragma unroll
    for (int e = 0; e < NE; e++) acc[e] = 0.0f;
#pragma unroll 4
    for (int j = 0; j < HD / 32; j++) {
        int h = lane + j * 32;
        float xv = xr[h];
#pragma unroll
        for (int e = 0; e < NE; e++) acc[e] += xv * gw[e * HD + h];
    }
#pragma unroll
    for (int e = 0; e < NE; e++)
#pragma unroll
        for (int o = 16; o > 0; o >>= 1)
            acc[e] += __shfl_xor_sync(0xFFFFFFFFu, acc[e], o);
    if (lane == 0) {
        int i0 = 0;
#pragma unroll
        for (int e = 1; e < NE; e++) if (acc[e] > acc[i0]) i0 = e;
        int i1 = (i0 == 0) ? 1 : 0;
#pragma unroll
        for (int e = 0; e < NE; e++) if (e != i0 && acc[e] > acc[i1]) i1 = e;
        float w0 = 1.0f / (1.0f + expf(acc[i1] - acc[i0]));
        float w1 = 1.0f - w0;
        int p0 = atomicAdd(&g_cnt[i0], 1);
        g_tok[i0 * TQ + p0] = gwarp;  g_wt[i0 * TQ + p0] = w0;
        int p1 = atomicAdd(&g_cnt[i1], 1);
        g_tok[i1 * TQ + p1] = gwarp;  g_wt[i1 * TQ + p1] = w1;
        g_se[gwarp * 2 + 0] = i0;  g_sp[gwarp * 2 + 0] = p0;
        g_se[gwarp * 2 + 1] = i1;  g_sp[gwarp * 2 + 1] = p1;
    }
}

__global__ void k_finalize() {
    if (threadIdx.x != 0 || blockIdx.x != 0) return;
    int o = 0; g_offs[0] = 0;
    for (int e = 0; e < NE; e++) { o += g_cnt[e]; g_offs[e + 1] = o; }
    int nt = 0;
    for (int e = 0; e < NE; e++)
        for (int r = 0; r < g_cnt[e] && nt < MAXTILES; r += 128) {
            g_tile_e[nt] = e; g_tile_r[nt] = r; nt++;
        }
    g_ntiles = nt;
}

// =====================================================================
// pass1: hid = silu(Xg @ W1) * (Xg @ W3)
// =====================================================================
__global__ void __launch_bounds__(256, 2)
k_pass1(const float* __restrict__ x, const float* __restrict__ w1,
        const float* __restrict__ w3) {
    const int mt = blockIdx.y;
    if (mt >= g_ntiles) return;
    const int e   = g_tile_e[mt];
    const int r0  = g_tile_r[mt];
    const int cnt = g_cnt[e];
    const int n0  = blockIdx.x * 64;

    extern __shared__ char smem[];
    const uint32_t sbase = smem_u32(smem);

    const int tid = threadIdx.x, lane = tid & 31, warp = tid >> 5;
    const int wm = warp >> 1, wn = warp & 1;
    const int gid = lane >> 2, tig = lane & 3;

    // A gather: 2 threads per 128B row
    const int arow = tid >> 1, ahalf = tid & 1;
    int tokr = 0;
    if (r0 + arow < cnt) tokr = g_tok[e * TQ + r0 + arow];
    const char* asrc = (const char*)(x + (size_t)tokr * HD) + ahalf * 64;
    const float* w1p = w1 + (size_t)e * HD * ID;
    const float* w3p = w3 + (size_t)e * HD * ID;

    // per-thread B copy coords: 512 16B-chunks per matrix / 256 thr = 2 iters
    // idx = tid + it*256 : row = idx>>4 (0..31), c = idx&15
    auto issue_stage = [&](int kc, int s) {
        const int k0 = kc * KC;
        const uint32_t sb = sbase + (uint32_t)s * P1_STAGE;
        // A
        {
            uint32_t dst = sb + P1_A_OFF + arow * P1_AROWB + ahalf * 64;
            const char* src = asrc + (size_t)k0 * 4;
#pragma unroll
            for (int q = 0; q < 4; q++) CP_ASYNC16(dst + q * 16, src + q * 16);
        }
        // B1 / B3
#pragma unroll
        for (int it = 0; it < 2; it++) {
            int idx = tid + it * 256;
            int row = idx >> 4, c = idx & 15;
            const char* s1 = (const char*)(w1p + (size_t)(k0 + row) * ID + n0) + c * 16;
            const char* s3 = (const char*)(w3p + (size_t)(k0 + row) * ID + n0) + c * 16;
            CP_ASYNC16(sb + P1_B1_OFF + row * P1_BROWB + c * 16, s1);
            CP_ASYNC16(sb + P1_B3_OFF + row * P1_BROWB + c * 16, s3);
        }
        CP_COMMIT();
    };

    float acc1[2][4][4], acc3[2][4][4];
#pragma unroll
    for (int mi = 0; mi < 2; mi++)
#pragma unroll
        for (int ni = 0; ni < 4; ni++)
#pragma unroll
            for (int q = 0; q < 4; q++) { acc1[mi][ni][q] = 0.f; acc3[mi][ni][q] = 0.f; }

    // ldmatrix per-lane base: rows rm..rm+15 for lanes&15, k half by lane>>4
    const int lrow = wm * 32 + (lane & 15);
    const int lkw  = (lane >> 4) * 4;

    issue_stage(0, 0);

    for (int kc = 0; kc < NK1; kc++) {
        const int buf = kc & 1;
        if (kc + 1 < NK1) { issue_stage(kc + 1, buf ^ 1); CP_WAIT(1); }
        else              { CP_WAIT(0); }
        __syncthreads();

        const uint32_t sb = sbase + (uint32_t)buf * P1_STAGE;
        const float* B1s = (const float*)(smem + (size_t)buf * P1_STAGE + P1_B1_OFF);
        const float* B3s = (const float*)(smem + (size_t)buf * P1_STAGE + P1_B3_OFF);
        const uint32_t abase = sb + P1_A_OFF + lrow * P1_AROWB + lkw * 4;

#pragma unroll
        for (int ks = 0; ks < 4; ks++) {
            const int kk = ks * 8;
            unsigned a[2][4];
#pragma unroll
            for (int mi = 0; mi < 2; mi++) {
                unsigned r0_, r1_, r2_, r3_;
                LDSM4(r0_, r1_, r2_, r3_, abase + mi * (16 * P1_AROWB) + kk * 4);
                a[mi][0] = u2tf(r0_); a[mi][1] = u2tf(r1_);
                a[mi][2] = u2tf(r2_); a[mi][3] = u2tf(r3_);
            }
#pragma unroll
            for (int ni = 0; ni < 4; ni++) {
                const int cc = wn * 32 + ni * 8 + gid;
                unsigned b10 = f2tf(B1s[(kk + tig) * 72 + cc]);
                unsigned b11 = f2tf(B1s[(kk + tig + 4) * 72 + cc]);
                unsigned b30 = f2tf(B3s[(kk + tig) * 72 + cc]);
                unsigned b31 = f2tf(B3s[(kk + tig + 4) * 72 + cc]);
#pragma unroll
                for (int mi = 0; mi < 2; mi++) {
                    mma_tf32(acc1[mi][ni], a[mi], b10, b11);
                    mma_tf32(acc3[mi][ni], a[mi], b30, b31);
                }
            }
        }
        __syncthreads();
    }

    // epilogue: SwiGLU -> g_hid
    const int gofs = g_offs[e];
#pragma unroll
    for (int mi = 0; mi < 2; mi++) {
#pragma unroll
        for (int ni = 0; ni < 4; ni++) {
            int col = n0 + wn * 32 + ni * 8 + tig * 2;
            int rl0 = r0 + wm * 32 + mi * 16 + gid;
            if (rl0 < cnt) {
                float2 h;
                h.x = silu(acc1[mi][ni][0]) * acc3[mi][ni][0];
                h.y = silu(acc1[mi][ni][1]) * acc3[mi][ni][1];
                *(float2*)&g_hid[(size_t)(gofs + rl0) * ID + col] = h;
            }
            int rl1 = rl0 + 8;
            if (rl1 < cnt) {
                float2 h;
                h.x = silu(acc1[mi][ni][2]) * acc3[mi][ni][2];
                h.y = silu(acc1[mi][ni][3]) * acc3[mi][ni][3];
                *(float2*)&g_hid[(size_t)(gofs + rl1) * ID + col] = h;
            }
        }
    }
}

// =====================================================================
// pass2: g_part[slot] = wt * (hid @ W2), tile M=128 N=128, warp 32x64
// =====================================================================
__global__ void __launch_bounds__(256, 2)
k_pass2(const float* __restrict__ w2) {
    const int mt = blockIdx.y;
    if (mt >= g_ntiles) return;
    const int e   = g_tile_e[mt];
    const int r0  = g_tile_r[mt];
    const int cnt = g_cnt[e];
    const int n0  = blockIdx.x * 128;
    const int gofs = g_offs[e];

    extern __shared__ char smem[];
    const uint32_t sbase = smem_u32(smem);

    const int tid = threadIdx.x, lane = tid & 31, warp = tid >> 5;
    const int wm = warp >> 1, wn = warp & 1;
    const int gid = lane >> 2, tig = lane & 3;

    const int arow = tid >> 1, ahalf = tid & 1;
    const int srow = (r0 + arow < cnt) ? (gofs + r0 + arow) : 0;
    const char* asrc = (const char*)(g_hid + (size_t)srow * ID) + ahalf * 64;
    const float* w2p = w2 + (size_t)e * ID * HD;

    auto issue_stage = [&](int kc, int s) {
        const int k0 = kc * KC;
        const uint32_t sb = sbase + (uint32_t)s * P2_STAGE;
        {
            uint32_t dst = sb + P2_A_OFF + arow * P1_AROWB + ahalf * 64;
            const char* src = asrc + (size_t)k0 * 4;
#pragma unroll
            for (int q = 0; q < 4; q++) CP_ASYNC16(dst + q * 16, src + q * 16);
        }
        // B: 32 rows x 512B = 1024 chunks / 256 thr = 4 iters
#pragma unroll
        for (int it = 0; it < 4; it++) {
            int idx = tid + it * 256;
            int row = idx >> 5, c = idx & 31;
            const char* s2 = (const char*)(w2p + (size_t)(k0 + row) * HD + n0) + c * 16;
            CP_ASYNC16(sb + P2_B_OFF + row * P2_BROWB + c * 16, s2);
        }
        CP_COMMIT();
    };

    float acc[2][8][4];
#pragma unroll
    for (int mi = 0; mi < 2; mi++)
#pragma unroll
        for (int ni = 0; ni < 8; ni++)
#pragma unroll
            for (int q = 0; q < 4; q++) acc[mi][ni][q] = 0.f;

    const int lrow = wm * 32 + (lane & 15);
    const int lkw  = (lane >> 4) * 4;

    issue_stage(0, 0);

    for (int kc = 0; kc < NK2; kc++) {
        const int buf = kc & 1;
        if (kc + 1 < NK2) { issue_stage(kc + 1, buf ^ 1); CP_WAIT(1); }
        else              { CP_WAIT(0); }
        __syncthreads();

        const uint32_t sb = sbase + (uint32_t)buf * P2_STAGE;
        const float* Bs = (const float*)(smem + (size_t)buf * P2_STAGE + P2_B_OFF);
        const uint32_t abase = sb + P2_A_OFF + lrow * P1_AROWB + lkw * 4;

#pragma unroll
        for (int ks = 0; ks < 4; ks++) {
            const int kk = ks * 8;
            unsigned a[2][4];
#pragma unroll
            for (int mi = 0; mi < 2; mi++) {
                unsigned r0_, r1_, r2_, r3_;
                LDSM4(r0_, r1_, r2_, r3_, abase + mi * (16 * P1_AROWB) + kk * 4);
                a[mi][0] = u2tf(r0_); a[mi][1] = u2tf(r1_);
                a[mi][2] = u2tf(r2_); a[mi][3] = u2tf(r3_);
            }
#pragma unroll
            for (int ni = 0; ni < 8; ni++) {
                const int cc = wn * 64 + ni * 8 + gid;
                unsigned b0 = f2tf(Bs[(kk + tig) * 136 + cc]);
                unsigned b1 = f2tf(Bs[(kk + tig + 4) * 136 + cc]);
#pragma unroll
                for (int mi = 0; mi < 2; mi++) mma_tf32(acc[mi][ni], a[mi], b0, b1);
            }
        }
        __syncthreads();
    }

    // epilogue: weighted store to g_part (no atomics)
#pragma unroll
    for (int mi = 0; mi < 2; mi++) {
#pragma unroll
        for (int half = 0; half < 2; half++) {
            int rl = r0 + wm * 32 + mi * 16 + gid + half * 8;
            if (rl >= cnt) continue;
            float wgt = g_wt[e * TQ + rl];
            float* op = g_part + (size_t)(gofs + rl) * HD;
#pragma unroll
            for (int ni = 0; ni < 8; ni++) {
                int col = n0 + wn * 64 + ni * 8 + tig * 2;
                float2 v;
                v.x = acc[mi][ni][half * 2 + 0] * wgt;
                v.y = acc[mi][ni][half * 2 + 1] * wgt;
                *(float2*)(op + col) = v;
            }
        }
    }
}

// combine: out[t] = part[slot0(t)] + part[slot1(t)]
__global__ void k_combine(float* __restrict__ out) {
    const int t = blockIdx.x;
    const int j = threadIdx.x;                 // 256 threads x float4 = 1024
    int e0 = g_se[t * 2 + 0], p0 = g_sp[t * 2 + 0];
    int e1 = g_se[t * 2 + 1], p1 = g_sp[t * 2 + 1];
    const float4* a = (const float4*)(g_part + (size_t)(g_offs[e0] + p0) * HD);
    const float4* b = (const float4*)(g_part + (size_t)(g_offs[e1] + p1) * HD);
    float4 va = a[j], vb = b[j];
    float4 o = make_float4(va.x + vb.x, va.y + vb.y, va.z + vb.z, va.w + vb.w);
    ((float4*)(out + (size_t)t * HD))[j] = o;
}

// ---------------- launch ----------------
extern "C" void kernel_launch(void* const* d_in, const int* in_sizes, int n_in,
                              void* d_out, int out_size) {
    const float* x  = (const float*)d_in[0];
    const float* gw = (const float*)d_in[1];
    const float* w1 = (const float*)d_in[2];
    const float* w3 = (const float*)d_in[3];
    const float* w2 = (const float*)d_in[4];
    float* out = (float*)d_out;

    cudaFuncSetAttribute(k_pass1, cudaFuncAttributeMaxDynamicSharedMemorySize, P1_SMEM);
    cudaFuncSetAttribute(k_pass2, cudaFuncAttributeMaxDynamicSharedMemorySize, P2_SMEM);

    k_zero<<<1, 32>>>();
    k_router<<<TQ / 8, 256>>>(x, gw);
    k_finalize<<<1, 1>>>();
    k_pass1<<<dim3(ID / 64, MAXTILES), 256, P1_SMEM>>>(x, w1, w3);
    k_pass2<<<dim3(HD / 128, MAXTILES), 256, P2_SMEM>>>(w2);
    k_combine<<<TQ, 256>>>(out);
}

// round 7
// speedup vs baseline: 2.4186x; 2.1761x over previous
#include <cuda_runtime.h>
#include <cuda_fp16.h>
#include <cstdint>

// Problem constants
#define TQ    16384
#define HD    1024
#define ID    3584
#define NE    8
#define MAXTILES 320
#define KC    32
#define NK1   (HD/KC)            // 32
#define NK2   (ID/KC)            // 112

// pass1 tile: M=128, N=64 per matrix (w1+w3), 8 warps (4 wm x 2 wn), warp 32x32
// pass2 tile: M=128, N=128, 8 warps (4 wm x 2 wn), warp 32x64

// smem layouts (bytes). fp16 halves everywhere.
#define P1_AROWB   80                          // 32 halves (64B) + 16B pad  (conflict-free ldmatrix)
#define P1_A_OFF   0
#define P1_B1_OFF  (128*80)                    // 10240
#define P1_BROWB   144                         // 64 halves (128B) + 16B pad
#define P1_B3_OFF  (P1_B1_OFF + 32*144)        // 14848
#define P1_STAGE   (P1_B3_OFF + 32*144)        // 19456
#define P1_NSTAGE  3
#define P1_SMEM    (P1_NSTAGE*P1_STAGE)        // 58368

#define P2_A_OFF   0
#define P2_B_OFF   (128*80)                    // 10240
#define P2_BROWB   272                         // 128 halves (256B) + 16B pad
#define P2_STAGE   (P2_B_OFF + 32*272)         // 18944
#define P2_NSTAGE  3
#define P2_SMEM    (P2_NSTAGE*P2_STAGE)        // 56832

// ---------------- device scratch ----------------
__device__ __half g_w1h[(size_t)NE * HD * ID];
__device__ __half g_w3h[(size_t)NE * HD * ID];
__device__ __half g_w2h[(size_t)NE * ID * HD];
__device__ __half g_xh [(size_t)TQ * HD];
__device__ __half g_hidh[(size_t)TQ * 2 * ID];   // SwiGLU intermediate (fp16)
__device__ float  g_part[(size_t)TQ * 2 * HD];   // weighted per-slot outputs
__device__ int    g_tok[NE * TQ];
__device__ float  g_wt [NE * TQ];
__device__ int    g_se [TQ * 2];
__device__ int    g_sp [TQ * 2];
__device__ int    g_cnt[NE];
__device__ int    g_offs[NE + 1];
__device__ int    g_tile_e[MAXTILES];
__device__ int    g_tile_r[MAXTILES];
__device__ int    g_ntiles;

// ---------------- helpers ----------------
__device__ __forceinline__ uint32_t smem_u32(const void* p) {
    uint32_t a;
    asm("{ .reg .u64 t; cvta.to.shared.u64 t, %1; cvt.u32.u64 %0, t; }" : "=r"(a) : "l"(p));
    return a;
}
__device__ __forceinline__ float silu(float x) { return x / (1.0f + __expf(-x)); }

__device__ __forceinline__ void mma_f16(float c[4], const unsigned a[4],
                                        unsigned b0, unsigned b1) {
    asm volatile(
        "mma.sync.aligned.m16n8k16.row.col.f32.f16.f16.f32 "
        "{%0,%1,%2,%3}, {%4,%5,%6,%7}, {%8,%9}, {%0,%1,%2,%3};"
        : "+f"(c[0]), "+f"(c[1]), "+f"(c[2]), "+f"(c[3])
        : "r"(a[0]), "r"(a[1]), "r"(a[2]), "r"(a[3]), "r"(b0), "r"(b1));
}

#define LDSM4(r0, r1, r2, r3, addr)                                              \
    asm volatile("ldmatrix.sync.aligned.m8n8.x4.shared.b16 {%0,%1,%2,%3}, [%4];" \
        : "=r"(r0), "=r"(r1), "=r"(r2), "=r"(r3) : "r"(addr))
#define LDSM4T(r0, r1, r2, r3, addr)                                                   \
    asm volatile("ldmatrix.sync.aligned.m8n8.x4.trans.shared.b16 {%0,%1,%2,%3}, [%4];" \
        : "=r"(r0), "=r"(r1), "=r"(r2), "=r"(r3) : "r"(addr))

#define CP_ASYNC16(dst, src) \
    asm volatile("cp.async.cg.shared.global [%0], [%1], 16;" :: "r"(dst), "l"(src))
#define CP_COMMIT()  asm volatile("cp.async.commit_group;" ::: "memory")
#define CP_WAIT(n)   asm volatile("cp.async.wait_group %0;" :: "n"(n) : "memory")

// ---------------- small kernels ----------------
__global__ void k_zero() { if (threadIdx.x < NE) g_cnt[threadIdx.x] = 0; }

// fp32 -> fp16 pre-round (grid-stride, float4 -> half2 x2)
__global__ void k_f2h(const float4* __restrict__ src, __half2* __restrict__ dst, int n4) {
    int i = blockIdx.x * blockDim.x + threadIdx.x;
    int stride = gridDim.x * blockDim.x;
    for (; i < n4; i += stride) {
        float4 v = src[i];
        dst[2 * i + 0] = __floats2half2_rn(v.x, v.y);
        dst[2 * i + 1] = __floats2half2_rn(v.z, v.w);
    }
}

__global__ void k_router(const float* __restrict__ x, const float* __restrict__ gw) {
    int gwarp = (blockIdx.x * blockDim.x + threadIdx.x) >> 5;
    int lane  = threadIdx.x & 31;
    if (gwarp >= TQ) return;
    const float* xr = x + (size_t)gwarp * HD;
    float acc[NE];
#pragma unroll
    for (int e = 0; e < NE; e++) acc[e] = 0.0f;
#pragma unroll 4
    for (int j = 0; j < HD / 32; j++) {
        int h = lane + j * 32;
        float xv = xr[h];
#pragma unroll
        for (int e = 0; e < NE; e++) acc[e] += xv * gw[e * HD + h];
    }
#pragma unroll
    for (int e = 0; e < NE; e++)
#pragma unroll
        for (int o = 16; o > 0; o >>= 1)
            acc[e] += __shfl_xor_sync(0xFFFFFFFFu, acc[e], o);
    if (lane == 0) {
        int i0 = 0;
#pragma unroll
        for (int e = 1; e < NE; e++) if (acc[e] > acc[i0]) i0 = e;
        int i1 = (i0 == 0) ? 1 : 0;
#pragma unroll
        for (int e = 0; e < NE; e++) if (e != i0 && acc[e] > acc[i1]) i1 = e;
        float w0 = 1.0f / (1.0f + expf(acc[i1] - acc[i0]));
        float w1 = 1.0f - w0;
        int p0 = atomicAdd(&g_cnt[i0], 1);
        g_tok[i0 * TQ + p0] = gwarp;  g_wt[i0 * TQ + p0] = w0;
        int p1 = atomicAdd(&g_cnt[i1], 1);
        g_tok[i1 * TQ + p1] = gwarp;  g_wt[i1 * TQ + p1] = w1;
        g_se[gwarp * 2 + 0] = i0;  g_sp[gwarp * 2 + 0] = p0;
        g_se[gwarp * 2 + 1] = i1;  g_sp[gwarp * 2 + 1] = p1;
    }
}

__global__ void k_finalize() {
    if (threadIdx.x != 0 || blockIdx.x != 0) return;
    int o = 0; g_offs[0] = 0;
    for (int e = 0; e < NE; e++) { o += g_cnt[e]; g_offs[e + 1] = o; }
    int nt = 0;
    for (int e = 0; e < NE; e++)
        for (int r = 0; r < g_cnt[e] && nt < MAXTILES; r += 128) {
            g_tile_e[nt] = e; g_tile_r[nt] = r; nt++;
        }
    g_ntiles = nt;
}

// =====================================================================
// pass1: hid = silu(Xg @ W1) * (Xg @ W3), fp16 mma m16n8k16
// =====================================================================
__global__ void __launch_bounds__(256, 2)
k_pass1() {
    const int mt = blockIdx.y;
    if (mt >= g_ntiles) return;
    const int e   = g_tile_e[mt];
    const int r0  = g_tile_r[mt];
    const int cnt = g_cnt[e];
    const int n0  = blockIdx.x * 64;

    extern __shared__ char smem[];
    const uint32_t sbase = smem_u32(smem);

    const int tid = threadIdx.x, lane = tid & 31, warp = tid >> 5;
    const int wm = warp >> 1, wn = warp & 1;
    const int gid = lane >> 2, tig = lane & 3;

    // A gather: 2 threads per row (32 halves = 64B)
    const int arow = tid >> 1, ahalf = tid & 1;
    int tokr = 0;
    if (r0 + arow < cnt) tokr = g_tok[e * TQ + r0 + arow];
    const char* asrc = (const char*)(g_xh + (size_t)tokr * HD) + ahalf * 32;
    const __half* w1p = g_w1h + (size_t)e * HD * ID;
    const __half* w3p = g_w3h + (size_t)e * HD * ID;

    // B copy coords: 32 rows x 8 chunks(16B) = 256 per matrix = 1 per thread
    const int brow = tid >> 3, bc = tid & 7;

    auto issue_stage = [&](int kc, int s) {
        const int k0 = kc * KC;
        const uint32_t sb = sbase + (uint32_t)s * P1_STAGE;
        uint32_t adst = sb + arow * P1_AROWB + ahalf * 32;
        const char* src = asrc + (size_t)k0 * 2;
        CP_ASYNC16(adst, src);
        CP_ASYNC16(adst + 16, src + 16);
        const char* s1 = (const char*)(w1p + (size_t)(k0 + brow) * ID + n0) + bc * 16;
        const char* s3 = (const char*)(w3p + (size_t)(k0 + brow) * ID + n0) + bc * 16;
        CP_ASYNC16(sb + P1_B1_OFF + brow * P1_BROWB + bc * 16, s1);
        CP_ASYNC16(sb + P1_B3_OFF + brow * P1_BROWB + bc * 16, s3);
        CP_COMMIT();
    };

    float acc1[2][4][4], acc3[2][4][4];
#pragma unroll
    for (int mi = 0; mi < 2; mi++)
#pragma unroll
        for (int ni = 0; ni < 4; ni++)
#pragma unroll
            for (int q = 0; q < 4; q++) { acc1[mi][ni][q] = 0.f; acc3[mi][ni][q] = 0.f; }

    // ldmatrix lane maps
    const int alrow = wm * 32 + (lane & 15);            // A rows
    const uint32_t aoff = (uint32_t)(alrow * P1_AROWB + (lane >> 4) * 16);
    const int blrow = (lane & 7) + 8 * ((lane >> 3) & 1);
    const uint32_t boff = (uint32_t)(blrow * P1_BROWB + (wn * 32 + 8 * (lane >> 4)) * 2);

    issue_stage(0, 0);
    issue_stage(1, 1);

    for (int kc = 0; kc < NK1; kc++) {
        if (kc + 1 < NK1) { CP_WAIT(1); } else { CP_WAIT(0); }
        __syncthreads();
        if (kc + 2 < NK1) issue_stage(kc + 2, (kc + 2) % P1_NSTAGE);

        const uint32_t sb = sbase + (uint32_t)(kc % P1_NSTAGE) * P1_STAGE;
        const uint32_t abase = sb + aoff;
        const uint32_t b1base = sb + P1_B1_OFF + boff;
        const uint32_t b3base = sb + P1_B3_OFF + boff;

#pragma unroll
        for (int ks = 0; ks < 2; ks++) {
            const int kk = ks * 16;
            unsigned a[2][4];
#pragma unroll
            for (int mi = 0; mi < 2; mi++)
                LDSM4(a[mi][0], a[mi][1], a[mi][2], a[mi][3],
                      abase + mi * (16 * P1_AROWB) + kk * 2);
#pragma unroll
            for (int p = 0; p < 2; p++) {
                unsigned r0_, r1_, r2_, r3_;
                LDSM4T(r0_, r1_, r2_, r3_, b1base + kk * P1_BROWB + p * 32);
#pragma unroll
                for (int mi = 0; mi < 2; mi++) {
                    mma_f16(acc1[mi][2 * p + 0], a[mi], r0_, r1_);
                    mma_f16(acc1[mi][2 * p + 1], a[mi], r2_, r3_);
                }
                LDSM4T(r0_, r1_, r2_, r3_, b3base + kk * P1_BROWB + p * 32);
#pragma unroll
                for (int mi = 0; mi < 2; mi++) {
                    mma_f16(acc3[mi][2 * p + 0], a[mi], r0_, r1_);
                    mma_f16(acc3[mi][2 * p + 1], a[mi], r2_, r3_);
                }
            }
        }
        __syncthreads();
    }

    // epilogue: SwiGLU -> g_hidh (fp16)
    const int gofs = g_offs[e];
#pragma unroll
    for (int mi = 0; mi < 2; mi++) {
#pragma unroll
        for (int ni = 0; ni < 4; ni++) {
            int col = n0 + wn * 32 + ni * 8 + tig * 2;
            int rl0 = r0 + wm * 32 + mi * 16 + gid;
            if (rl0 < cnt) {
                __half2 h = __floats2half2_rn(
                    silu(acc1[mi][ni][0]) * acc3[mi][ni][0],
                    silu(acc1[mi][ni][1]) * acc3[mi][ni][1]);
                *(__half2*)&g_hidh[(size_t)(gofs + rl0) * ID + col] = h;
            }
            int rl1 = rl0 + 8;
            if (rl1 < cnt) {
                __half2 h = __floats2half2_rn(
                    silu(acc1[mi][ni][2]) * acc3[mi][ni][2],
                    silu(acc1[mi][ni][3]) * acc3[mi][ni][3]);
                *(__half2*)&g_hidh[(size_t)(gofs + rl1) * ID + col] = h;
            }
        }
    }
}

// =====================================================================
// pass2: g_part[slot] = wt * (hid @ W2), fp16 mma, tile M=128 N=128
// =====================================================================
__global__ void __launch_bounds__(256, 2)
k_pass2() {
    const int mt = blockIdx.y;
    if (mt >= g_ntiles) return;
    const int e   = g_tile_e[mt];
    const int r0  = g_tile_r[mt];
    const int cnt = g_cnt[e];
    const int n0  = blockIdx.x * 128;
    const int gofs = g_offs[e];

    extern __shared__ char smem[];
    const uint32_t sbase = smem_u32(smem);

    const int tid = threadIdx.x, lane = tid & 31, warp = tid >> 5;
    const int wm = warp >> 1, wn = warp & 1;
    const int gid = lane >> 2, tig = lane & 3;

    const int arow = tid >> 1, ahalf = tid & 1;
    const int srow = (r0 + arow < cnt) ? (gofs + r0 + arow) : 0;
    const char* asrc = (const char*)(g_hidh + (size_t)srow * ID) + ahalf * 32;
    const __half* w2p = g_w2h + (size_t)e * ID * HD;

    auto issue_stage = [&](int kc, int s) {
        const int k0 = kc * KC;
        const uint32_t sb = sbase + (uint32_t)s * P2_STAGE;
        uint32_t adst = sb + arow * P1_AROWB + ahalf * 32;
        const char* src = asrc + (size_t)k0 * 2;
        CP_ASYNC16(adst, src);
        CP_ASYNC16(adst + 16, src + 16);
        // B: 32 rows x 16 chunks = 512 / 256 thr = 2 iters
#pragma unroll
        for (int it = 0; it < 2; it++) {
            int idx = tid + it * 256;
            int row = idx >> 4, c = idx & 15;
            const char* s2 = (const char*)(w2p + (size_t)(k0 + row) * HD + n0) + c * 16;
            CP_ASYNC16(sb + P2_B_OFF + row * P2_BROWB + c * 16, s2);
        }
        CP_COMMIT();
    };

    float acc[2][8][4];
#pragma unroll
    for (int mi = 0; mi < 2; mi++)
#pragma unroll
        for (int ni = 0; ni < 8; ni++)
#pragma unroll
            for (int q = 0; q < 4; q++) acc[mi][ni][q] = 0.f;

    const int alrow = wm * 32 + (lane & 15);
    const uint32_t aoff = (uint32_t)(alrow * P1_AROWB + (lane >> 4) * 16);
    const int blrow = (lane & 7) + 8 * ((lane >> 3) & 1);
    const uint32_t boff = (uint32_t)(blrow * P2_BROWB + (wn * 64 + 8 * (lane >> 4)) * 2);

    issue_stage(0, 0);
    issue_stage(1, 1);

    for (int kc = 0; kc < NK2; kc++) {
        if (kc + 1 < NK2) { CP_WAIT(1); } else { CP_WAIT(0); }
        __syncthreads();
        if (kc + 2 < NK2) issue_stage(kc + 2, (kc + 2) % P2_NSTAGE);

        const uint32_t sb = sbase + (uint32_t)(kc % P2_NSTAGE) * P2_STAGE;
        const uint32_t abase = sb + aoff;
        const uint32_t bbase = sb + P2_B_OFF + boff;

#pragma unroll
        for (int ks = 0; ks < 2; ks++) {
            const int kk = ks * 16;
            unsigned a[2][4];
#pragma unroll
            for (int mi = 0; mi < 2; mi++)
                LDSM4(a[mi][0], a[mi][1], a[mi][2], a[mi][3],
                      abase + mi * (16 * P1_AROWB) + kk * 2);
#pragma unroll
            for (int p = 0; p < 4; p++) {
                unsigned r0_, r1_, r2_, r3_;
                LDSM4T(r0_, r1_, r2_, r3_, bbase + kk * P2_BROWB + p * 32);
#pragma unroll
                for (int mi = 0; mi < 2; mi++) {
                    mma_f16(acc[mi][2 * p + 0], a[mi], r0_, r1_);
                    mma_f16(acc[mi][2 * p + 1], a[mi], r2_, r3_);
                }
            }
        }
        __syncthreads();
    }

    // epilogue: weighted store to g_part (fp32, no atomics)
#pragma unroll
    for (int mi = 0; mi < 2; mi++) {
#pragma unroll
        for (int half = 0; half < 2; half++) {
            int rl = r0 + wm * 32 + mi * 16 + gid + half * 8;
            if (rl >= cnt) continue;
            float wgt = g_wt[e * TQ + rl];
            float* op = g_part + (size_t)(gofs + rl) * HD;
#pragma unroll
            for (int ni = 0; ni < 8; ni++) {
                int col = n0 + wn * 64 + ni * 8 + tig * 2;
                float2 v;
                v.x = acc[mi][ni][half * 2 + 0] * wgt;
                v.y = acc[mi][ni][half * 2 + 1] * wgt;
                *(float2*)(op + col) = v;
            }
        }
    }
}

// combine: out[t] = part[slot0(t)] + part[slot1(t)]
__global__ void k_combine(float* __restrict__ out) {
    const int t = blockIdx.x;
    const int j = threadIdx.x;                 // 256 threads x float4 = 1024
    int e0 = g_se[t * 2 + 0], p0 = g_sp[t * 2 + 0];
    int e1 = g_se[t * 2 + 1], p1 = g_sp[t * 2 + 1];
    const float4* a = (const float4*)(g_part + (size_t)(g_offs[e0] + p0) * HD);
    const float4* b = (const float4*)(g_part + (size_t)(g_offs[e1] + p1) * HD);
    float4 va = a[j], vb = b[j];
    float4 o = make_float4(va.x + vb.x, va.y + vb.y, va.z + vb.z, va.w + vb.w);
    ((float4*)(out + (size_t)t * HD))[j] = o;
}

// ---------------- launch ----------------
extern "C" void kernel_launch(void* const* d_in, const int* in_sizes, int n_in,
                              void* d_out, int out_size) {
    const float* x  = (const float*)d_in[0];
    const float* gw = (const float*)d_in[1];
    const float* w1 = (const float*)d_in[2];
    const float* w3 = (const float*)d_in[3];
    const float* w2 = (const float*)d_in[4];
    float* out = (float*)d_out;

    cudaFuncSetAttribute(k_pass1, cudaFuncAttributeMaxDynamicSharedMemorySize, P1_SMEM);
    cudaFuncSetAttribute(k_pass2, cudaFuncAttributeMaxDynamicSharedMemorySize, P2_SMEM);

    k_zero<<<1, 32>>>();
    k_router<<<TQ / 8, 256>>>(x, gw);
    k_finalize<<<1, 1>>>();

    // pre-round fp32 -> fp16 (weights + activations); idempotent math, graph-safe
    const int W4 = NE * HD * ID / 4;           // 7,340,032
    const int X4 = TQ * HD / 4;                // 4,194,304
    __half2* w1h; cudaGetSymbolAddress((void**)&w1h, g_w1h);
    __half2* w3h; cudaGetSymbolAddress((void**)&w3h, g_w3h);
    __half2* w2h; cudaGetSymbolAddress((void**)&w2h, g_w2h);
    __half2* xh;  cudaGetSymbolAddress((void**)&xh,  g_xh);
    k_f2h<<<4096, 256>>>((const float4*)w1, w1h, W4);
    k_f2h<<<4096, 256>>>((const float4*)w3, w3h, W4);
    k_f2h<<<4096, 256>>>((const float4*)w2, w2h, W4);
    k_f2h<<<4096, 256>>>((const float4*)x,  xh,  X4);

    k_pass1<<<dim3(ID / 64, MAXTILES), 256, P1_SMEM>>>();
    k_pass2<<<dim3(HD / 128, MAXTILES), 256, P2_SMEM>>>();
    k_combine<<<TQ, 256>>>(out);
}